// round 6
// baseline (speedup 1.0000x reference)
#include <cuda_runtime.h>
#include <cuda_bf16.h>
#include <math.h>
#include <cstdint>

#define N_NODES 100000
#define D 128

// Scratch: degrees [set][0=out(src)/1=in(dst)][node], Y = feats @ W
__device__ float g_deg[2][2][N_NODES];
__device__ float g_y[(size_t)N_NODES * D];

// ---------------- degree histograms (both sets) ----------------
__global__ void degree_kernel(const int* __restrict__ sp, const int* __restrict__ dp,
                              const int* __restrict__ sn, const int* __restrict__ dn, int E) {
    int i = blockIdx.x * blockDim.x + threadIdx.x;
    if (i >= E) return;
    atomicAdd(&g_deg[0][0][sp[i]], 1.0f);
    atomicAdd(&g_deg[0][1][dp[i]], 1.0f);
    atomicAdd(&g_deg[1][0][sn[i]], 1.0f);
    atomicAdd(&g_deg[1][1][dn[i]], 1.0f);
}

// ---------------- Y = feats @ W via mma.sync bf16 (hi/lo split, fp32 accum) ----------------
// smem: Ah/Al = A tile [128][132] bf16, Bh/Bl = W^T [128][132] bf16 (pitch 132 kills conflicts)
#define PITCH 132
#define TILE_BYTES (128 * PITCH * 2)   // 33792
#define SM_AH 0
#define SM_AL (TILE_BYTES)
#define SM_BH (2 * TILE_BYTES)
#define SM_BL (3 * TILE_BYTES)
#define SM_TOTAL (4 * TILE_BYTES)      // 135168

__device__ __forceinline__ void mma_bf16(float& c0, float& c1, float& c2, float& c3,
                                         uint32_t a0, uint32_t a1, uint32_t a2, uint32_t a3,
                                         uint32_t b0, uint32_t b1) {
    asm volatile(
        "mma.sync.aligned.m16n8k16.row.col.f32.bf16.bf16.f32 "
        "{%0,%1,%2,%3}, {%4,%5,%6,%7}, {%8,%9}, {%0,%1,%2,%3};"
        : "+f"(c0), "+f"(c1), "+f"(c2), "+f"(c3)
        : "r"(a0), "r"(a1), "r"(a2), "r"(a3), "r"(b0), "r"(b1));
}

__global__ void __launch_bounds__(256, 1) ygemm_mma_kernel(const float* __restrict__ feats,
                                                           const float* __restrict__ W) {
    extern __shared__ __align__(16) char smc[];
    __nv_bfloat16* Ah = reinterpret_cast<__nv_bfloat16*>(smc + SM_AH);
    __nv_bfloat16* Al = reinterpret_cast<__nv_bfloat16*>(smc + SM_AL);
    __nv_bfloat16* Bh = reinterpret_cast<__nv_bfloat16*>(smc + SM_BH);
    __nv_bfloat16* Bl = reinterpret_cast<__nv_bfloat16*>(smc + SM_BL);

    int tid = threadIdx.x;
    int wid = tid >> 5;
    int lane = tid & 31;
    int row0 = blockIdx.x * D;

    // W -> Bh/Bl transposed: Bs[n][k] = W[k][n]   (coalesced global read over n)
    for (int idx = tid; idx < D * D; idx += 256) {
        int k = idx >> 7, n = idx & 127;
        float x = W[idx];
        __nv_bfloat16 h = __float2bfloat16(x);
        __nv_bfloat16 l = __float2bfloat16(x - __bfloat162float(h));
        Bh[n * PITCH + k] = h;
        Bl[n * PITCH + k] = l;
    }
    // feats tile -> Ah/Al (float4 coalesced reads, zero-pad past N)
    {
        const float4* Av = reinterpret_cast<const float4*>(feats);
        for (int idx = tid; idx < D * (D / 4); idx += 256) {
            int row = idx >> 5, c4 = idx & 31;
            int grow = row0 + row;
            float4 v = make_float4(0.f, 0.f, 0.f, 0.f);
            if (grow < N_NODES) v = Av[(size_t)grow * (D / 4) + c4];
            float vals[4] = {v.x, v.y, v.z, v.w};
            #pragma unroll
            for (int j = 0; j < 4; j++) {
                int col = c4 * 4 + j;
                float x = vals[j];
                __nv_bfloat16 h = __float2bfloat16(x);
                __nv_bfloat16 l = __float2bfloat16(x - __bfloat162float(h));
                Ah[row * PITCH + col] = h;
                Al[row * PITCH + col] = l;
            }
        }
    }
    __syncthreads();

    int qr = lane >> 2;        // 0..7
    int qc = (lane & 3) * 2;   // 0,2,4,6
    int r0 = 16 * wid + qr;    // warp rows 16*wid .. +15

    float acc[16][4];
    #pragma unroll
    for (int j = 0; j < 16; j++)
        #pragma unroll
        for (int q = 0; q < 4; q++) acc[j][q] = 0.0f;

    const uint32_t* Ah32 = reinterpret_cast<const uint32_t*>(Ah);
    const uint32_t* Al32 = reinterpret_cast<const uint32_t*>(Al);
    const uint32_t* Bh32 = reinterpret_cast<const uint32_t*>(Bh);
    const uint32_t* Bl32 = reinterpret_cast<const uint32_t*>(Bl);

    #pragma unroll
    for (int ks = 0; ks < 8; ks++) {
        int kk = ks * 16 + qc;           // bf16 col, even => b32 index = (row*PITCH+kk)/2
        int i00 = (r0 * PITCH + kk) >> 1;
        int i10 = ((r0 + 8) * PITCH + kk) >> 1;
        uint32_t ah0 = Ah32[i00],     ah1 = Ah32[i10];
        uint32_t ah2 = Ah32[i00 + 4], ah3 = Ah32[i10 + 4];   // +8 bf16 = +4 b32
        uint32_t al0 = Al32[i00],     al1 = Al32[i10];
        uint32_t al2 = Al32[i00 + 4], al3 = Al32[i10 + 4];

        #pragma unroll
        for (int j = 0; j < 16; j++) {
            int n = 8 * j + qr;
            int ib0 = (n * PITCH + kk) >> 1;
            uint32_t bh0 = Bh32[ib0], bh1 = Bh32[ib0 + 4];
            uint32_t bl0 = Bl32[ib0], bl1 = Bl32[ib0 + 4];
            mma_bf16(acc[j][0], acc[j][1], acc[j][2], acc[j][3], ah0, ah1, ah2, ah3, bh0, bh1);
            mma_bf16(acc[j][0], acc[j][1], acc[j][2], acc[j][3], ah0, ah1, ah2, ah3, bl0, bl1);
            mma_bf16(acc[j][0], acc[j][1], acc[j][2], acc[j][3], al0, al1, al2, al3, bh0, bh1);
        }
    }

    // store: c0,c1 -> row r0, cols 8j+qc..+1 ; c2,c3 -> row r0+8
    int grow_a = row0 + r0;
    int grow_b = grow_a + 8;
    #pragma unroll
    for (int j = 0; j < 16; j++) {
        int col = 8 * j + qc;
        if (grow_a < N_NODES)
            *reinterpret_cast<float2*>(&g_y[(size_t)grow_a * D + col]) = make_float2(acc[j][0], acc[j][1]);
        if (grow_b < N_NODES)
            *reinterpret_cast<float2*>(&g_y[(size_t)grow_b * D + col]) = make_float2(acc[j][2], acc[j][3]);
    }
}

// ---------------- edge scatter: out[dst] += Y[src] * ns[src] * nd[dst] ----------------
__global__ void scatter_kernel(const int* __restrict__ src, const int* __restrict__ dst,
                               int E, float* __restrict__ outset, int set) {
    int w = (blockIdx.x * blockDim.x + threadIdx.x) >> 5;
    int lane = threadIdx.x & 31;
    int e0 = w * 4;
    if (e0 >= E) return;
    int n = E - e0; if (n > 4) n = 4;

    const float4* Yv = reinterpret_cast<const float4*>(&g_y[0]);

    int s[4], d[4];
    #pragma unroll
    for (int i = 0; i < 4; i++) {
        int e = e0 + ((i < n) ? i : 0);
        s[i] = src[e];
        d[i] = dst[e];
    }
    float dgs[4], dgd[4];
    #pragma unroll
    for (int i = 0; i < 4; i++) {
        dgs[i] = g_deg[set][0][s[i]];
        dgd[i] = g_deg[set][1][d[i]];
    }
    float4 v[4];
    #pragma unroll
    for (int i = 0; i < 4; i++) v[i] = Yv[(size_t)s[i] * (D / 4) + lane];

    float c[4];
    #pragma unroll
    for (int i = 0; i < 4; i++) {
        float ns = (dgs[i] > 0.0f) ? rsqrtf(dgs[i]) : 0.0f;
        float nd = (dgd[i] > 0.0f) ? rsqrtf(dgd[i]) : 0.0f;
        c[i] = ns * nd;
    }
    #pragma unroll
    for (int i = 0; i < 4; i++) {
        if (i >= n) break;
        float4 t = v[i];
        t.x *= c[i]; t.y *= c[i]; t.z *= c[i]; t.w *= c[i];
        float* a = &outset[(size_t)d[i] * D + lane * 4];
        asm volatile("red.global.add.v4.f32 [%0], {%1, %2, %3, %4};"
                     :: "l"(a), "f"(t.x), "f"(t.y), "f"(t.z), "f"(t.w) : "memory");
    }
}

// ---------------- epilogue: out = prelu(out + b) in-place ----------------
__global__ void epilogue_kernel(float* __restrict__ out, const float* __restrict__ b,
                                const float* __restrict__ prelu_a) {
    size_t idx = (size_t)blockIdx.x * blockDim.x + threadIdx.x;
    size_t total = 2ull * N_NODES * (D / 4);
    if (idx >= total) return;

    int c4 = (int)(idx & 31);
    float pa = prelu_a[0];

    float4 v = reinterpret_cast<float4*>(out)[idx];
    float4 bb = reinterpret_cast<const float4*>(b)[c4];

    float h0 = v.x + bb.x;
    float h1 = v.y + bb.y;
    float h2 = v.z + bb.z;
    float h3 = v.w + bb.w;
    v.x = (h0 > 0.f) ? h0 : pa * h0;
    v.y = (h1 > 0.f) ? h1 : pa * h1;
    v.z = (h2 > 0.f) ? h2 : pa * h2;
    v.w = (h3 > 0.f) ? h3 : pa * h3;
    reinterpret_cast<float4*>(out)[idx] = v;
}

extern "C" void kernel_launch(void* const* d_in, const int* in_sizes, int n_in,
                              void* d_out, int out_size) {
    const float* feats   = (const float*)d_in[0];
    const float* W       = (const float*)d_in[1];
    const float* b       = (const float*)d_in[2];
    const float* prelu_a = (const float*)d_in[3];
    const int* src_pos   = (const int*)d_in[4];
    const int* dst_pos   = (const int*)d_in[5];
    const int* src_neg   = (const int*)d_in[6];
    const int* dst_neg   = (const int*)d_in[7];
    int E = in_sizes[4];
    float* out = (float*)d_out;

    void* deg_ptr = nullptr;
    cudaGetSymbolAddress(&deg_ptr, g_deg);
    cudaMemsetAsync(deg_ptr, 0, sizeof(float) * 2 * 2 * N_NODES);
    cudaMemsetAsync(out, 0, sizeof(float) * 2ull * N_NODES * D);

    degree_kernel<<<(E + 255) / 256, 256>>>(src_pos, dst_pos, src_neg, dst_neg, E);

    cudaFuncSetAttribute(ygemm_mma_kernel, cudaFuncAttributeMaxDynamicSharedMemorySize, SM_TOTAL);
    ygemm_mma_kernel<<<(N_NODES + D - 1) / D, 256, SM_TOTAL>>>(feats, W);

    int warps = (E + 3) / 4;
    int sblocks = (warps + 7) / 8;
    float* out_pos = out;
    float* out_neg = out + (size_t)N_NODES * D;
    scatter_kernel<<<sblocks, 256>>>(src_pos, dst_pos, E, out_pos, 0);
    scatter_kernel<<<sblocks, 256>>>(src_neg, dst_neg, E, out_neg, 1);

    size_t etotal = 2ull * N_NODES * (D / 4);
    epilogue_kernel<<<(int)((etotal + 255) / 256), 256>>>(out, b, prelu_a);
}